// round 13
// baseline (speedup 1.0000x reference)
#include <cuda_runtime.h>

// deblurNet: out = x @ W.T with W complex DIAGONAL:
//   out[b,i] = (xr + j*xi)[b,i] * W[i,i]
//
// R12 conclusion: wallclock (6.62-6.66us) is insensitive to 1.6us of ncu
// body-time variation across three structurally different designs ->
// fixed launch/replay overhead dominates; body is hidden. This round keeps
// the best structure (R11: block = 16 cols x 64 batches, diag gathered
// exactly once chip-wide = 18,432 scattered loads, x prefetched before the
// barrier) with two zero-risk tweaks: compile-time output mode (no runtime
// branch) and __stcs streaming stores (output never re-read; keep x + diag
// L2-resident across graph replays).

#define TOT   589824   // B*N complex elements (64 * 9216)
#define NDIM  9216     // N = 96*96
#define DSTR  9217     // diagonal stride in dense [N,N] f32 storage
#define BATCH 64
#define TC    16               // columns per block (gathered ONCE chip-wide)
#define NBLK  (NDIM / TC)      // 576 blocks

template <int MODE>
__global__ void __launch_bounds__(256)
deblur_tiled(const float* __restrict__ xr,
             const float* __restrict__ xi,
             const float* __restrict__ wr,
             const float* __restrict__ wi,
             float* __restrict__ out) {
    __shared__ float2 s_diag[TC];

    const int tid  = threadIdx.x;
    const int col0 = blockIdx.x * TC;

    // Phase 1a: diagonal gather (32 scattered LDG.32 per block; 18,432
    // chip-wide). Max offset (NDIM-1)*DSTR = N^2-1: in-bounds.
    if (tid < TC) {
        const long long d = (long long)(col0 + tid) * DSTR;
        s_diag[tid] = make_float2(__ldg(wr + d), __ldg(wi + d));
    }

    // Phase 1b: prefetch x BEFORE the barrier — independent of the gather,
    // so BAR release waits on max(gather, x-load), not the sum.
    const int cg = tid & 3;                // 0..3  -> cols col0 + cg*4 .. +3
    const int b  = tid >> 2;               // 0..63 -> batch row
    const int i   = col0 + cg * 4;
    const int idx = b * NDIM + i;          // max TOT-4: in-bounds
    const float4 ar = *reinterpret_cast<const float4*>(xr + idx);
    const float4 ai = *reinterpret_cast<const float4*>(xi + idx);

    __syncthreads();

    // Phase 2: broadcast smem reads (64 b-threads share each cg -> N=1).
    const float2 w0 = s_diag[cg * 4 + 0];
    const float2 w1 = s_diag[cg * 4 + 1];
    const float2 w2 = s_diag[cg * 4 + 2];
    const float2 w3 = s_diag[cg * 4 + 3];

    const float o0r = fmaf(ar.x, w0.x, -ai.x * w0.y), o0i = fmaf(ar.x, w0.y, ai.x * w0.x);
    const float o1r = fmaf(ar.y, w1.x, -ai.y * w1.y), o1i = fmaf(ar.y, w1.y, ai.y * w1.x);
    const float o2r = fmaf(ar.z, w2.x, -ai.z * w2.y), o2i = fmaf(ar.z, w2.y, ai.z * w2.x);
    const float o3r = fmaf(ar.w, w3.x, -ai.w * w3.y), o3i = fmaf(ar.w, w3.y, ai.w * w3.x);

    if (MODE == 1) {
        // Interleaved re/im (f32 view of complex64): 2*TOT floats.
        float4* o = reinterpret_cast<float4*>(out) + (idx >> 1);
        __stcs(o + 0, make_float4(o0r, o0i, o1r, o1i));
        __stcs(o + 1, make_float4(o2r, o2i, o3r, o3i));
    } else {
        // Real part only: TOT floats.
        __stcs(reinterpret_cast<float4*>(out + idx),
               make_float4(o0r, o1r, o2r, o3r));
    }
}

extern "C" void kernel_launch(void* const* d_in, const int* in_sizes, int n_in,
                              void* d_out, int out_size) {
    if (n_in < 4) return;

    // Inputs are f32 at reported element counts (confirmed R6-R12 passes).
    // Smaller-size pair = x (B*N), larger pair = W (N*N); real before imag.
    long long smin = -1;
    for (int k = 0; k < 4; ++k) {
        long long s = (long long)in_sizes[k];
        if (smin < 0 || s < smin) smin = s;
    }
    const float* xs[2] = {nullptr, nullptr};
    const float* ws[2] = {nullptr, nullptr};
    int nx = 0, nw = 0;
    for (int k = 0; k < 4; ++k) {
        if ((long long)in_sizes[k] == smin && nx < 2) xs[nx++] = (const float*)d_in[k];
        else if (nw < 2)                              ws[nw++] = (const float*)d_in[k];
    }
    if (nx < 2 || nw < 2) return;

    // Output mode strictly bounded by out_size (4-byte elements).
    if ((long long)out_size >= 2LL * TOT) {
        deblur_tiled<1><<<NBLK, 256>>>(xs[0], xs[1], ws[0], ws[1], (float*)d_out);
    } else {
        deblur_tiled<0><<<NBLK, 256>>>(xs[0], xs[1], ws[0], ws[1], (float*)d_out);
    }
}

// round 14
// speedup vs baseline: 1.0386x; 1.0386x over previous
#include <cuda_runtime.h>

// deblurNet: out = x @ W.T with W complex DIAGONAL:
//   out[b,i] = (xr + j*xi)[b,i] * W[i,i]
//
// Converged design (best measured: R11, 6.624us). Findings baked in:
//  - wallclock floor ~6.6us is launch/graph-replay overhead; body hidden
//    (ncu body varied 8.3-10.4us across designs, wallclock flat 6.62-6.88)
//  - time tracks scattered-load count; here each diag entry is gathered
//    exactly ONCE chip-wide (18,432 loads)
//  - R13 profile showed MODE 0 (real-part-only output) is the live path:
//    the harness compares TOT f32 elements. Mode-0 computes only real
//    outputs (4 FMA/thread instead of 8).
//  - __stcs regressed (R13): plain stores.
//
// Block = 16 cols x 64 batches, 576 blocks x 256 threads. x prefetched
// before the barrier so BAR release waits on max(gather, x-load).

#define TOT   589824   // B*N complex elements (64 * 9216)
#define NDIM  9216     // N = 96*96
#define DSTR  9217     // diagonal stride in dense [N,N] f32 storage
#define TC    16               // columns per block (gathered ONCE chip-wide)
#define NBLK  (NDIM / TC)      // 576 blocks

template <int MODE>   // 0: real part only (TOT floats), 1: interleaved re/im
__global__ void __launch_bounds__(256)
deblur_tiled(const float* __restrict__ xr,
             const float* __restrict__ xi,
             const float* __restrict__ wr,
             const float* __restrict__ wi,
             float* __restrict__ out) {
    __shared__ float2 s_diag[TC];

    const int tid  = threadIdx.x;
    const int col0 = blockIdx.x * TC;

    // Phase 1a: diagonal gather (32 scattered LDG.32 per block).
    // Max offset (NDIM-1)*DSTR = N^2-1: in-bounds.
    if (tid < TC) {
        const long long d = (long long)(col0 + tid) * DSTR;
        s_diag[tid] = make_float2(__ldg(wr + d), __ldg(wi + d));
    }

    // Phase 1b: prefetch x BEFORE the barrier (independent of the gather).
    const int cg = tid & 3;                // 0..3  -> cols col0 + cg*4 .. +3
    const int b  = tid >> 2;               // 0..63 -> batch row
    const int i   = col0 + cg * 4;
    const int idx = b * NDIM + i;          // max TOT-4: in-bounds
    const float4 ar = *reinterpret_cast<const float4*>(xr + idx);
    const float4 ai = *reinterpret_cast<const float4*>(xi + idx);

    __syncthreads();

    // Phase 2: broadcast smem reads (64 b-threads share each cg -> N=1).
    const float2 w0 = s_diag[cg * 4 + 0];
    const float2 w1 = s_diag[cg * 4 + 1];
    const float2 w2 = s_diag[cg * 4 + 2];
    const float2 w3 = s_diag[cg * 4 + 3];

    const float o0r = fmaf(ar.x, w0.x, -ai.x * w0.y);
    const float o1r = fmaf(ar.y, w1.x, -ai.y * w1.y);
    const float o2r = fmaf(ar.z, w2.x, -ai.z * w2.y);
    const float o3r = fmaf(ar.w, w3.x, -ai.w * w3.y);

    if (MODE == 1) {
        // Interleaved re/im (f32 view of complex64): 2*TOT floats.
        const float o0i = fmaf(ar.x, w0.y, ai.x * w0.x);
        const float o1i = fmaf(ar.y, w1.y, ai.y * w1.x);
        const float o2i = fmaf(ar.z, w2.y, ai.z * w2.x);
        const float o3i = fmaf(ar.w, w3.y, ai.w * w3.x);
        float4* o = reinterpret_cast<float4*>(out) + (idx >> 1);
        o[0] = make_float4(o0r, o0i, o1r, o1i);
        o[1] = make_float4(o2r, o2i, o3r, o3i);
    } else {
        // Real part only: TOT floats (the live path per R13 profile).
        *reinterpret_cast<float4*>(out + idx) = make_float4(o0r, o1r, o2r, o3r);
    }
}

extern "C" void kernel_launch(void* const* d_in, const int* in_sizes, int n_in,
                              void* d_out, int out_size) {
    if (n_in < 4) return;

    // Inputs are f32 at reported element counts (confirmed R6-R13 passes).
    // Smaller-size pair = x (B*N), larger pair = W (N*N); real before imag.
    long long smin = -1;
    for (int k = 0; k < 4; ++k) {
        long long s = (long long)in_sizes[k];
        if (smin < 0 || s < smin) smin = s;
    }
    const float* xs[2] = {nullptr, nullptr};
    const float* ws[2] = {nullptr, nullptr};
    int nx = 0, nw = 0;
    for (int k = 0; k < 4; ++k) {
        if ((long long)in_sizes[k] == smin && nx < 2) xs[nx++] = (const float*)d_in[k];
        else if (nw < 2)                              ws[nw++] = (const float*)d_in[k];
    }
    if (nx < 2 || nw < 2) return;

    // Output mode strictly bounded by out_size (4-byte elements).
    if ((long long)out_size >= 2LL * TOT) {
        deblur_tiled<1><<<NBLK, 256>>>(xs[0], xs[1], ws[0], ws[1], (float*)d_out);
    } else {
        deblur_tiled<0><<<NBLK, 256>>>(xs[0], xs[1], ws[0], ws[1], (float*)d_out);
    }
}